// round 6
// baseline (speedup 1.0000x reference)
#include <cuda_runtime.h>
#include <cuda_bf16.h>

// MotionPrimitiveDecoder: logits[b,n,t,a] = dot(df[b,n,t,a,:], z[b,n,:]) + cd[t,a] - mean_fa(cd[t,:])
// where cd = ctx_features . u_ctx_w.  The frenet/polyline projection term is constant
// across (t,a) for fixed (b,n) and cancels exactly in u - u_mean, so
// map_polylines / idx / pts are never read.
//
// Shapes: B=32, N=64, T=40, A=6, Z=64, C=3.
//
// R6: two-kernel split. bias_kernel precomputes (cd - mean) into __device__ scratch;
//     stream_kernel is 100% barrier-free / smem-free pure streaming (bias read hits L2).

#define B_DIM 32
#define N_DIM 64
#define T_DIM 40
#define A_DIM 6
#define Z_DIM 64
#define TA_DIM (T_DIM * A_DIM)   // 240
#define BN_DIM (B_DIM * N_DIM)   // 2048

__device__ float g_bias[BN_DIM * TA_DIM];   // 1.97 MB scratch

// ---------------------------------------------------------------------------
// Kernel 1: bias[bn,ta] = cd[ta] - mean_feasible(cd[t,:])
// ---------------------------------------------------------------------------
__global__ __launch_bounds__(256) void bias_kernel(
    const float* __restrict__ ctx,   // [BN,TA,3]
    const int*   __restrict__ fa,    // [BN,TA]
    const float* __restrict__ w)     // [3]
{
    __shared__ float cd_s[TA_DIM];
    __shared__ float mean_s[T_DIM];

    const int bn  = blockIdx.x;
    const int tid = threadIdx.x;
    const long cb = (long)bn * TA_DIM * 3;
    const long fb = (long)bn * TA_DIM;

    const float w0 = __ldg(w), w1 = __ldg(w + 1), w2 = __ldg(w + 2);

    if (tid < TA_DIM) {
        const float* c = ctx + cb + (long)tid * 3;
        cd_s[tid] = c[0] * w0 + c[1] * w1 + c[2] * w2;
    }
    __syncthreads();

    if (tid < T_DIM) {
        const int* f = fa + fb + tid * A_DIM;
        float s_all = 0.f, s_f = 0.f;
        int cnt = 0;
        #pragma unroll
        for (int a = 0; a < A_DIM; a++) {
            float cda = cd_s[tid * A_DIM + a];
            s_all += cda;
            if (f[a]) { s_f += cda; cnt++; }
        }
        mean_s[tid] = cnt ? (s_f / (float)cnt) : (s_all / (float)A_DIM);
    }
    __syncthreads();

    if (tid < TA_DIM) {
        g_bias[fb + tid] = cd_s[tid] - mean_s[tid / A_DIM];
    }
}

// ---------------------------------------------------------------------------
// Kernel 2: pure streaming, no barriers, no smem.
// Each warp covers 2 rows per slot (half-warp per row), 15 slots,
// rolling 5-deep load pipeline.
// ---------------------------------------------------------------------------
__global__ __launch_bounds__(256) void stream_kernel(
    const float* __restrict__ z,     // [BN,Z]
    const float* __restrict__ df,    // [BN,TA,Z]
    float* __restrict__ out)         // [BN,TA]
{
    const int bn  = blockIdx.x;
    const int tid = threadIdx.x;
    const int warp = tid >> 5;
    const int lane = tid & 31;
    const int half = lane >> 4;
    const int hl   = lane & 15;

    const long fb  = (long)bn * TA_DIM;
    const int  row0 = warp * 2 + half;               // this thread's base row

    // df row pointer in float4 units; consecutive slots stride 16 rows = 256 float4
    const float4* p4 = (const float4*)(df + (long)bn * TA_DIM * Z_DIM)
                       + (long)row0 * 16 + hl;

    // ---- prime pipeline: first 5 df loads issued before anything else ----
    float4 v[5];
    #pragma unroll
    for (int j = 0; j < 5; j++) v[j] = p4[(long)j * 256];

    // z directly from gmem (256B per bn, L1/L2 broadcast across half-warps)
    const float4 zv = ((const float4*)(z + (long)bn * Z_DIM))[hl];

    #pragma unroll
    for (int j = 0; j < 15; j++) {
        const int ta = j * 16 + row0;
        const float4 x = v[j % 5];

        // bias load issued at slot top (L2-resident), off the shuffle chain
        float bb = 0.f;
        if (hl == 0) bb = g_bias[fb + ta];

        if (j + 5 < 15) v[j % 5] = p4[(long)(j + 5) * 256];

        float p = x.x * zv.x + x.y * zv.y + x.z * zv.z + x.w * zv.w;
        p += __shfl_xor_sync(0xFFFFFFFFu, p, 1);
        p += __shfl_xor_sync(0xFFFFFFFFu, p, 2);
        p += __shfl_xor_sync(0xFFFFFFFFu, p, 4);
        p += __shfl_xor_sync(0xFFFFFFFFu, p, 8);

        if (hl == 0) out[fb + ta] = p + bb;
    }
}

extern "C" void kernel_launch(void* const* d_in, const int* in_sizes, int n_in,
                              void* d_out, int out_size) {
    // metadata order: map_polylines, idx, pts, z, decision_features,
    //                 ctx_features, feasible_actions, u_ctx_w, u_ctx_b
    const float* z   = (const float*)d_in[3];
    const float* df  = (const float*)d_in[4];
    const float* ctx = (const float*)d_in[5];
    const int*   fa  = (const int*)d_in[6];
    const float* w   = (const float*)d_in[7];
    float* out = (float*)d_out;

    bias_kernel<<<BN_DIM, 256>>>(ctx, fa, w);
    stream_kernel<<<BN_DIM, 256>>>(z, df, out);
}

// round 7
// speedup vs baseline: 1.1250x; 1.1250x over previous
#include <cuda_runtime.h>
#include <cuda_bf16.h>

// MotionPrimitiveDecoder: logits[b,n,t,a] = dot(df[b,n,t,a,:], z[b,n,:]) + cd[t,a] - mean_fa(cd[t,:])
// where cd = ctx_features . u_ctx_w.  The frenet/polyline projection term is constant
// across (t,a) for fixed (b,n) and cancels exactly in u - u_mean, so
// map_polylines / idx / pts are never read.
//
// Shapes: B=32, N=64, T=40, A=6, Z=64, C=3.
//
// R7: persistent one-wave fused kernel. 592 CTAs (148x4), each loops 3-4 bn units.
//     Rolling 5-deep df pipeline refills ACROSS bn boundaries (slots 10-14 of unit i
//     prefetch unit i+1's first rows), so the load pipe never drains until the final
//     unit. Double-buffered smem bias; next unit's prologue hides under in-flight loads.

#define B_DIM 32
#define N_DIM 64
#define T_DIM 40
#define A_DIM 6
#define Z_DIM 64
#define TA_DIM (T_DIM * A_DIM)   // 240
#define BN_DIM (B_DIM * N_DIM)   // 2048
#define GRID   592               // 148 * 4, one full wave at 4 CTAs/SM
#define EXTRA  (BN_DIM - 3 * GRID)  // 272 CTAs run a 4th unit

__global__ __launch_bounds__(256) void mpd_kernel(
    const float* __restrict__ z,     // [BN,Z]
    const float* __restrict__ df,    // [BN,TA,Z]
    const float* __restrict__ ctx,   // [BN,TA,3]
    const int*   __restrict__ fa,    // [BN,TA]
    const float* __restrict__ w,     // [3]
    float* __restrict__ out)         // [BN,TA]
{
    __shared__ float cd_s[2][TA_DIM];
    __shared__ float mean_s[2][T_DIM];

    const int tid  = threadIdx.x;
    const int warp = tid >> 5;
    const int lane = tid & 31;
    const int half = lane >> 4;
    const int hl   = lane & 15;
    const int row0 = warp * 2 + half;        // base row for this thread's half-warp

    const float w0 = __ldg(w), w1 = __ldg(w + 1), w2 = __ldg(w + 2);

    const int it_count = (blockIdx.x < EXTRA) ? 4 : 3;

    int bn = blockIdx.x;
    // df pointer for this thread's lane position within unit bn
    const float4* dfp = (const float4*)(df + (long)bn * TA_DIM * Z_DIM)
                        + (long)row0 * 16 + hl;

    // prime the pipeline for the first unit
    float4 v[5];
    #pragma unroll
    for (int j = 0; j < 5; j++) v[j] = dfp[(long)j * 256];

    for (int it = 0; ; it++) {
        const int buf = it & 1;
        const long fb = (long)bn * TA_DIM;

        // z for this unit (256B, issued before the barriers)
        const float4 zv = ((const float4*)(z + (long)bn * Z_DIM))[hl];

        // ---- bias prologue (hidden under the in-flight df loads) ----
        if (tid < TA_DIM) {
            const float* c = ctx + (long)bn * TA_DIM * 3 + (long)tid * 3;
            cd_s[buf][tid] = c[0] * w0 + c[1] * w1 + c[2] * w2;
        }
        __syncthreads();

        if (tid < T_DIM) {
            const int* f = fa + fb + tid * A_DIM;
            float s_all = 0.f, s_f = 0.f;
            int cnt = 0;
            #pragma unroll
            for (int a = 0; a < A_DIM; a++) {
                float cda = cd_s[buf][tid * A_DIM + a];
                s_all += cda;
                if (f[a]) { s_f += cda; cnt++; }
            }
            mean_s[buf][tid] = cnt ? (s_f / (float)cnt) : (s_all / (float)A_DIM);
        }
        __syncthreads();

        // ---- streaming: 15 slots; slots 0-9 refill this unit, 10-14 refill next ----
        const bool has_next = (it + 1 < it_count);
        const int bn_next = bn + GRID;
        const float4* dfp_next = (const float4*)(df + (long)bn_next * TA_DIM * Z_DIM)
                                 + (long)row0 * 16 + hl;

        #pragma unroll
        for (int j = 0; j < 15; j++) {
            const int ta = j * 16 + row0;
            const float4 x = v[j % 5];

            if (j < 10) {
                v[j % 5] = dfp[(long)(j + 5) * 256];
            } else if (has_next) {
                v[j % 5] = dfp_next[(long)(j - 10) * 256];   // cross-unit prefetch
            }

            float p = x.x * zv.x + x.y * zv.y + x.z * zv.z + x.w * zv.w;
            p += __shfl_xor_sync(0xFFFFFFFFu, p, 1);
            p += __shfl_xor_sync(0xFFFFFFFFu, p, 2);
            p += __shfl_xor_sync(0xFFFFFFFFu, p, 4);
            p += __shfl_xor_sync(0xFFFFFFFFu, p, 8);

            if (hl == 0) {
                out[fb + ta] = p + cd_s[buf][ta] - mean_s[buf][ta / A_DIM];
            }
        }

        if (!has_next) break;
        bn = bn_next;
        dfp = dfp_next;
    }
}

extern "C" void kernel_launch(void* const* d_in, const int* in_sizes, int n_in,
                              void* d_out, int out_size) {
    // metadata order: map_polylines, idx, pts, z, decision_features,
    //                 ctx_features, feasible_actions, u_ctx_w, u_ctx_b
    const float* z   = (const float*)d_in[3];
    const float* df  = (const float*)d_in[4];
    const float* ctx = (const float*)d_in[5];
    const int*   fa  = (const int*)d_in[6];
    const float* w   = (const float*)d_in[7];
    float* out = (float*)d_out;

    mpd_kernel<<<GRID, 256>>>(z, df, ctx, fa, w, out);
}